// round 1
// baseline (speedup 1.0000x reference)
#include <cuda_runtime.h>
#include <cuda_bf16.h>
#include <cstdint>
#include <cstddef>

// ---------------------------------------------------------------------------
// GTrXLCell fused pipeline for GB300 (sm_103a), round 1: tf32 mma.sync GEMMs.
//
// Key algebraic simplification: seq_len==1 => softmax(scores) == 1 exactly,
// so ctx == v. We never compute q or k (saves 69 GFLOP).
//
// Pipeline:
//   G1: x    = x_t @ W_proj^T + b_proj                    [4096,2048]
//   L1: qn   = LN(x; ln1)                                  [4096,2048]
//   G2: v    = qn @ Wv^T + bv      (Wv = in_proj_w rows [4096:6144])
//   G3: hhat = sig(ga)*h_prev + sig(gb)*(v @ out_w^T + out_b)
//   L2: y    = LN(hhat; ln2)
//   G4: t    = gelu_exact(y @ ffn_w1^T + ffn_b1)           [4096,8192]
//   G5: out  = hhat + t @ ffn_w2^T + ffn_b2  (stored twice: (h_new,h_new))
// ---------------------------------------------------------------------------

#define B_DIM     4096
#define D_MODEL   2048
#define D_FF      8192

// scratch (static device globals: allocation-free rule)
__device__ float g_x   [(size_t)B_DIM * D_MODEL];
__device__ float g_qn  [(size_t)B_DIM * D_MODEL];
__device__ float g_v   [(size_t)B_DIM * D_MODEL];
__device__ float g_hhat[(size_t)B_DIM * D_MODEL];
__device__ float g_y   [(size_t)B_DIM * D_MODEL];
__device__ float g_t   [(size_t)B_DIM * D_FF];

__device__ __forceinline__ float to_tf32(float x) {
    uint32_t u;
    asm("cvt.rna.tf32.f32 %0, %1;" : "=r"(u) : "f"(x));
    return __uint_as_float(u);
}

__device__ __forceinline__ void mma_tf32(float c[4], const uint32_t a[4], const uint32_t b[2]) {
    asm volatile(
        "mma.sync.aligned.m16n8k8.row.col.f32.tf32.tf32.f32 "
        "{%0,%1,%2,%3}, {%4,%5,%6,%7}, {%8,%9}, {%0,%1,%2,%3};\n"
        : "+f"(c[0]), "+f"(c[1]), "+f"(c[2]), "+f"(c[3])
        : "r"(a[0]), "r"(a[1]), "r"(a[2]), "r"(a[3]), "r"(b[0]), "r"(b[1]));
}

__device__ __forceinline__ float sigmoidf_(float x) { return 1.0f / (1.0f + expf(-x)); }
__device__ __forceinline__ float gelu_exact(float x) {
    return 0.5f * x * (1.0f + erff(x * 0.70710678118654752f));
}

// ---------------------------------------------------------------------------
// Tiled tf32 GEMM: C[M,N] = A[M,K] @ Bw[N,K]^T + bias, with fused epilogue.
// BM=BN=128, BK=32. 256 threads = 8 warps (2 x 4), warp tile 64x32.
// MODE 0: +bias
// MODE 1: hhat = sig(ga[col])*aux[r,c] + sig(gb[col])*(acc+bias)
// MODE 2: gelu_exact(acc+bias)
// MODE 3: (acc+bias) + aux[r,c], stored to C and (optionally) C2
// ---------------------------------------------------------------------------
template <int MODE>
__global__ void __launch_bounds__(256, 2) gemm_tf32_ep(
    const float* __restrict__ A, const float* __restrict__ Bw,
    const float* __restrict__ bias, float* __restrict__ C,
    int M, int N, int K,
    const float* __restrict__ aux,
    const float* __restrict__ ga, const float* __restrict__ gb,
    float* __restrict__ C2)
{
    constexpr int BM = 128, BN = 128, BK = 32;
    constexpr int PAD = 4;                    // 36 floats per row: conflict-free frags
    __shared__ float As[BM][BK + PAD];
    __shared__ float Bs[BN][BK + PAD];

    const int tid  = threadIdx.x;
    const int warp = tid >> 5;
    const int lane = tid & 31;
    const int wm = warp >> 2;                 // 0..1   (M direction, 64 rows each)
    const int wn = warp & 3;                  // 0..3   (N direction, 32 cols each)
    const int gr = lane >> 2;                 // group row 0..7
    const int tg = lane & 3;                  // thread-in-group 0..3

    const int block_row = blockIdx.y * BM;
    const int block_col = blockIdx.x * BN;

    const float* Ablk = A  + (size_t)block_row * K;
    const float* Bblk = Bw + (size_t)block_col * K;

    float acc[4][4][4];
    #pragma unroll
    for (int mi = 0; mi < 4; mi++)
        #pragma unroll
        for (int ni = 0; ni < 4; ni++)
            #pragma unroll
            for (int r = 0; r < 4; r++)
                acc[mi][ni][r] = 0.0f;

    const int kTiles = K / BK;
    for (int kt = 0; kt < kTiles; ++kt) {
        const int k0 = kt * BK;
        // stage A and B tiles (convert to tf32 once here)
        #pragma unroll
        for (int i = 0; i < 4; i++) {
            const int idx = tid + i * 256;      // 0..1023
            const int r = idx >> 3;             // 0..127
            const int c = (idx & 7) * 4;        // 0..28
            float4 fa = *reinterpret_cast<const float4*>(Ablk + (size_t)r * K + k0 + c);
            As[r][c + 0] = to_tf32(fa.x); As[r][c + 1] = to_tf32(fa.y);
            As[r][c + 2] = to_tf32(fa.z); As[r][c + 3] = to_tf32(fa.w);
            float4 fb = *reinterpret_cast<const float4*>(Bblk + (size_t)r * K + k0 + c);
            Bs[r][c + 0] = to_tf32(fb.x); Bs[r][c + 1] = to_tf32(fb.y);
            Bs[r][c + 2] = to_tf32(fb.z); Bs[r][c + 3] = to_tf32(fb.w);
        }
        __syncthreads();

        #pragma unroll
        for (int ks = 0; ks < BK / 8; ++ks) {
            const int kk = ks * 8;
            uint32_t af[4][4];
            uint32_t bf[4][2];
            #pragma unroll
            for (int mi = 0; mi < 4; mi++) {
                const int r = wm * 64 + mi * 16 + gr;
                af[mi][0] = __float_as_uint(As[r    ][kk + tg    ]);
                af[mi][1] = __float_as_uint(As[r + 8][kk + tg    ]);
                af[mi][2] = __float_as_uint(As[r    ][kk + tg + 4]);
                af[mi][3] = __float_as_uint(As[r + 8][kk + tg + 4]);
            }
            #pragma unroll
            for (int ni = 0; ni < 4; ni++) {
                const int c = wn * 32 + ni * 8 + gr;
                bf[ni][0] = __float_as_uint(Bs[c][kk + tg    ]);
                bf[ni][1] = __float_as_uint(Bs[c][kk + tg + 4]);
            }
            #pragma unroll
            for (int mi = 0; mi < 4; mi++)
                #pragma unroll
                for (int ni = 0; ni < 4; ni++)
                    mma_tf32(acc[mi][ni], af[mi], bf[ni]);
        }
        __syncthreads();
    }

    // epilogue
    #pragma unroll
    for (int mi = 0; mi < 4; mi++) {
        #pragma unroll
        for (int ni = 0; ni < 4; ni++) {
            const int col = block_col + wn * 32 + ni * 8 + 2 * tg;
            const float b0 = bias[col], b1 = bias[col + 1];
            #pragma unroll
            for (int h = 0; h < 2; h++) {
                const int row = block_row + wm * 64 + mi * 16 + gr + h * 8;
                float v0 = acc[mi][ni][2 * h + 0] + b0;
                float v1 = acc[mi][ni][2 * h + 1] + b1;
                const size_t off = (size_t)row * N + col;
                if (MODE == 1) {
                    const float sa0 = sigmoidf_(ga[col]),     sa1 = sigmoidf_(ga[col + 1]);
                    const float sb0 = sigmoidf_(gb[col]),     sb1 = sigmoidf_(gb[col + 1]);
                    v0 = sa0 * aux[off]     + sb0 * v0;
                    v1 = sa1 * aux[off + 1] + sb1 * v1;
                } else if (MODE == 2) {
                    v0 = gelu_exact(v0);
                    v1 = gelu_exact(v1);
                } else if (MODE == 3) {
                    v0 += aux[off];
                    v1 += aux[off + 1];
                }
                float2 o = make_float2(v0, v1);
                *reinterpret_cast<float2*>(&C[off]) = o;
                if (MODE == 3 && C2 != nullptr)
                    *reinterpret_cast<float2*>(&C2[off]) = o;
            }
        }
    }
}

// ---------------------------------------------------------------------------
// LayerNorm over D=2048, one block per row, 256 threads x 8 elements.
// ---------------------------------------------------------------------------
__global__ void __launch_bounds__(256) ln2048_kernel(
    const float* __restrict__ x, const float* __restrict__ g,
    const float* __restrict__ b, float* __restrict__ out)
{
    constexpr int D = 2048;
    const int row = blockIdx.x;
    const int tid = threadIdx.x;
    const float4* xr = reinterpret_cast<const float4*>(x + (size_t)row * D);

    float4 v0 = xr[tid];
    float4 v1 = xr[tid + 256];
    float s  = v0.x + v0.y + v0.z + v0.w + v1.x + v1.y + v1.z + v1.w;
    float ss = v0.x * v0.x + v0.y * v0.y + v0.z * v0.z + v0.w * v0.w
             + v1.x * v1.x + v1.y * v1.y + v1.z * v1.z + v1.w * v1.w;

    #pragma unroll
    for (int o = 16; o > 0; o >>= 1) {
        s  += __shfl_xor_sync(0xFFFFFFFFu, s,  o);
        ss += __shfl_xor_sync(0xFFFFFFFFu, ss, o);
    }
    __shared__ float sh_s[8], sh_ss[8];
    const int warp = tid >> 5, lane = tid & 31;
    if (lane == 0) { sh_s[warp] = s; sh_ss[warp] = ss; }
    __syncthreads();
    float ts = 0.0f, tss = 0.0f;
    #pragma unroll
    for (int i = 0; i < 8; i++) { ts += sh_s[i]; tss += sh_ss[i]; }

    const float mean = ts * (1.0f / D);
    const float var  = tss * (1.0f / D) - mean * mean;
    const float inv  = rsqrtf(var + 1e-5f);

    const float4* g4 = reinterpret_cast<const float4*>(g);
    const float4* b4 = reinterpret_cast<const float4*>(b);
    float4* o4 = reinterpret_cast<float4*>(out + (size_t)row * D);

    float4 ga0 = g4[tid],       gb0 = b4[tid];
    float4 ga1 = g4[tid + 256], gb1 = b4[tid + 256];
    float4 r0, r1;
    r0.x = (v0.x - mean) * inv * ga0.x + gb0.x;
    r0.y = (v0.y - mean) * inv * ga0.y + gb0.y;
    r0.z = (v0.z - mean) * inv * ga0.z + gb0.z;
    r0.w = (v0.w - mean) * inv * ga0.w + gb0.w;
    r1.x = (v1.x - mean) * inv * ga1.x + gb1.x;
    r1.y = (v1.y - mean) * inv * ga1.y + gb1.y;
    r1.z = (v1.z - mean) * inv * ga1.z + gb1.z;
    r1.w = (v1.w - mean) * inv * ga1.w + gb1.w;
    o4[tid]       = r0;
    o4[tid + 256] = r1;
}

// ---------------------------------------------------------------------------
extern "C" void kernel_launch(void* const* d_in, const int* in_sizes, int n_in,
                              void* d_out, int out_size)
{
    const float* x_t    = (const float*)d_in[0];
    const float* h_prev = (const float*)d_in[1];
    const float* W_proj = (const float*)d_in[2];
    const float* b_proj = (const float*)d_in[3];
    const float* in_w   = (const float*)d_in[4];
    const float* in_b   = (const float*)d_in[5];
    const float* out_w  = (const float*)d_in[6];
    const float* out_b  = (const float*)d_in[7];
    const float* ln1_g  = (const float*)d_in[8];
    const float* ln1_b  = (const float*)d_in[9];
    const float* ln2_g  = (const float*)d_in[10];
    const float* ln2_b  = (const float*)d_in[11];
    const float* gate_a = (const float*)d_in[12];
    const float* gate_b = (const float*)d_in[13];
    const float* ffn_w1 = (const float*)d_in[14];
    const float* ffn_b1 = (const float*)d_in[15];
    const float* ffn_w2 = (const float*)d_in[16];
    const float* ffn_b2 = (const float*)d_in[17];
    float* out = (float*)d_out;

    float *px, *pqn, *pv, *phh, *py, *pt;
    cudaGetSymbolAddress((void**)&px,  g_x);
    cudaGetSymbolAddress((void**)&pqn, g_qn);
    cudaGetSymbolAddress((void**)&pv,  g_v);
    cudaGetSymbolAddress((void**)&phh, g_hhat);
    cudaGetSymbolAddress((void**)&py,  g_y);
    cudaGetSymbolAddress((void**)&pt,  g_t);

    const dim3 blk(256);
    const dim3 grid_d (D_MODEL / 128, B_DIM / 128);   // 16 x 32
    const dim3 grid_ff(D_FF    / 128, B_DIM / 128);   // 64 x 32

    // G1: x = x_t @ W_proj^T + b_proj
    gemm_tf32_ep<0><<<grid_d, blk>>>(x_t, W_proj, b_proj, px,
                                     B_DIM, D_MODEL, 1024,
                                     nullptr, nullptr, nullptr, nullptr);
    // L1: qn = LN(x)
    ln2048_kernel<<<B_DIM, 256>>>(px, ln1_g, ln1_b, pqn);

    // G2: v = qn @ Wv^T + bv   (v slice of in_proj: rows [2*D_MODEL, 3*D_MODEL))
    gemm_tf32_ep<0><<<grid_d, blk>>>(pqn,
                                     in_w + (size_t)2 * D_MODEL * D_MODEL,
                                     in_b + 2 * D_MODEL, pv,
                                     B_DIM, D_MODEL, D_MODEL,
                                     nullptr, nullptr, nullptr, nullptr);

    // G3: hhat = sig(ga)*h_prev + sig(gb)*(v @ out_w^T + out_b)
    gemm_tf32_ep<1><<<grid_d, blk>>>(pv, out_w, out_b, phh,
                                     B_DIM, D_MODEL, D_MODEL,
                                     h_prev, gate_a, gate_b, nullptr);

    // L2: y = LN(hhat)
    ln2048_kernel<<<B_DIM, 256>>>(phh, ln2_g, ln2_b, py);

    // G4: t = gelu(y @ ffn_w1^T + ffn_b1)
    gemm_tf32_ep<2><<<grid_ff, blk>>>(py, ffn_w1, ffn_b1, pt,
                                      B_DIM, D_FF, D_MODEL,
                                      nullptr, nullptr, nullptr, nullptr);

    // G5: h_new = hhat + t @ ffn_w2^T + ffn_b2 ; duplicated output (h_new, h_new)
    float* out2 = (out_size >= 2 * B_DIM * D_MODEL) ? (out + (size_t)B_DIM * D_MODEL)
                                                    : nullptr;
    gemm_tf32_ep<3><<<grid_d, blk>>>(pt, ffn_w2, ffn_b2, out,
                                     B_DIM, D_MODEL, D_FF,
                                     phh, nullptr, nullptr, out2);
}

// round 3
// speedup vs baseline: 2.0936x; 2.0936x over previous
#include <cuda_runtime.h>
#include <cuda_fp16.h>
#include <cstdint>
#include <cstddef>

// ---------------------------------------------------------------------------
// GTrXLCell round 3: fp16 mma.sync(m16n8k16) + ldmatrix + cp.async pipeline.
// (tcgen05 rejected by harness toolchain: virtual arch compute_103 w/o 'a'.)
//
// seq_len==1 => softmax==1 => ctx == v (q,k dead code).
//   conv: weights fp32->fp16, x_t->fp16
//   G1: x    = x16 @ wp16^T + b_proj          -> fp32 g_x
//   L1: qn16 = LN(g_x; ln1)                    (fp16)
//   G2: v16  = qn16 @ wv16^T + bv              (fp16)
//   G3: hhat = sig(ga)*h_prev + sig(gb)*(v16 @ wo16^T + out_b) -> fp32
//   L2: y16  = LN(hhat; ln2)                   (fp16)
//   G4: t16  = gelu(y16 @ w1_16^T + b1)        (fp16)
//   G5: out  = hhat + t16 @ w2_16^T + b2       (fp32, dual store)
// ---------------------------------------------------------------------------

#define B_DIM     4096
#define D_MODEL   2048
#define D_FF      8192

// fp32 scratch
__device__ float g_x   [(size_t)B_DIM * D_MODEL];
__device__ float g_hhat[(size_t)B_DIM * D_MODEL];
// fp16 activations
__device__ __half g_x16 [(size_t)B_DIM * 1024];
__device__ __half g_qn16[(size_t)B_DIM * D_MODEL];
__device__ __half g_v16 [(size_t)B_DIM * D_MODEL];
__device__ __half g_y16 [(size_t)B_DIM * D_MODEL];
__device__ __half g_t16 [(size_t)B_DIM * D_FF];
// fp16 weights
__device__ __half g_wp16 [(size_t)D_MODEL * 1024];
__device__ __half g_wv16 [(size_t)D_MODEL * D_MODEL];
__device__ __half g_wo16 [(size_t)D_MODEL * D_MODEL];
__device__ __half g_w1_16[(size_t)D_FF * D_MODEL];
__device__ __half g_w2_16[(size_t)D_MODEL * D_FF];

// ------------------------------ helpers -----------------------------------
__device__ __forceinline__ uint32_t smem_u32(const void* p) {
    uint32_t a;
    asm("{ .reg .u64 t; cvta.to.shared.u64 t, %1; cvt.u32.u64 %0, t; }"
        : "=r"(a) : "l"(p));
    return a;
}
__device__ __forceinline__ void cp16(uint32_t dst, const void* src) {
    asm volatile("cp.async.cg.shared.global [%0], [%1], 16;"
                 :: "r"(dst), "l"(src));
}
#define CP_COMMIT() asm volatile("cp.async.commit_group;" ::: "memory")
#define CP_WAIT1()  asm volatile("cp.async.wait_group 1;" ::: "memory")
#define CP_WAIT0()  asm volatile("cp.async.wait_group 0;" ::: "memory")

__device__ __forceinline__ void ldsm_x4(uint32_t& r0, uint32_t& r1,
                                        uint32_t& r2, uint32_t& r3, uint32_t addr) {
    asm volatile("ldmatrix.sync.aligned.m8n8.x4.shared.b16 {%0,%1,%2,%3}, [%4];"
                 : "=r"(r0), "=r"(r1), "=r"(r2), "=r"(r3) : "r"(addr));
}
__device__ __forceinline__ void mma_f16(float c[4], const uint32_t a[4],
                                        const uint32_t b[2]) {
    asm volatile(
        "mma.sync.aligned.m16n8k16.row.col.f32.f16.f16.f32 "
        "{%0,%1,%2,%3}, {%4,%5,%6,%7}, {%8,%9}, {%0,%1,%2,%3};\n"
        : "+f"(c[0]), "+f"(c[1]), "+f"(c[2]), "+f"(c[3])
        : "r"(a[0]), "r"(a[1]), "r"(a[2]), "r"(a[3]), "r"(b[0]), "r"(b[1]));
}
__device__ __forceinline__ float sigmoidf_(float x) { return 1.0f / (1.0f + expf(-x)); }
__device__ __forceinline__ float gelu_exact(float x) {
    return 0.5f * x * (1.0f + erff(x * 0.70710678118654752f));
}

// ---------------------------------------------------------------------------
// fp16 GEMM: C[M,N] = A[M,K] @ Bw[N,K]^T + bias (+epilogue).
// BM=BN=128, BK=32(halves), 3-stage cp.async pipeline, 256 thr = 8 warps 2x4.
// Warp tile 64x32: 4 m-frags(16) x 4 n-frags(8), k16 steps.
// MODE 0:+bias  1:gate  2:gelu  3:+aux residual (dual fp32 store)
// ---------------------------------------------------------------------------
constexpr int BM = 128, BN = 128, BKH = 32;   // BKH in halves
constexpr int LDT = 40;                       // padded row stride (halves)
constexpr int TILE_HALVES = BM * LDT;         // 5120 per operand
constexpr uint32_t STAGE_BYTES = 2u * TILE_HALVES * 2u;   // A+B = 20480 B
constexpr int STAGES = 3;
constexpr uint32_t GSMEM = STAGES * STAGE_BYTES;          // 61440 B

template <int MODE, int OUT32, int OUT16>
__global__ void __launch_bounds__(256, 2) gemm16(
    const __half* __restrict__ A, const __half* __restrict__ Bw,
    const float* __restrict__ bias,
    float* __restrict__ C32, __half* __restrict__ C16, float* __restrict__ C32b,
    const float* __restrict__ aux,
    const float* __restrict__ ga, const float* __restrict__ gb,
    int N, int K)
{
    extern __shared__ char smraw[];
    const uint32_t sbase = smem_u32(smraw);

    const int tid  = threadIdx.x;
    const int warp = tid >> 5;
    const int lane = tid & 31;
    const int wm = warp >> 2;          // 0..1
    const int wn = warp & 3;           // 0..3
    const int gr = lane >> 2;          // 0..7
    const int tg = lane & 3;           // 0..3

    const int block_row = blockIdx.y * BM;
    const int block_col = blockIdx.x * BN;
    const int KT = K / BKH;

    // staging copy source/dest (2 chunks of 8 halves per operand per thread)
    const int ch0_row = tid >> 2;            // 0..63
    const int ch0_col = (tid & 3) * 8;       // 0,8,16,24
    const int ch1_row = ch0_row + 64;

    const __half* Ag0 = A  + (size_t)(block_row + ch0_row) * K + ch0_col;
    const __half* Ag1 = A  + (size_t)(block_row + ch1_row) * K + ch0_col;
    const __half* Bg0 = Bw + (size_t)(block_col + ch0_row) * K + ch0_col;
    const __half* Bg1 = Bw + (size_t)(block_col + ch1_row) * K + ch0_col;
    const uint32_t dA0 = (uint32_t)(ch0_row * LDT + ch0_col) * 2u;
    const uint32_t dA1 = (uint32_t)(ch1_row * LDT + ch0_col) * 2u;
    const uint32_t dB0 = (uint32_t)(TILE_HALVES + ch0_row * LDT + ch0_col) * 2u;
    const uint32_t dB1 = (uint32_t)(TILE_HALVES + ch1_row * LDT + ch0_col) * 2u;

    // ldmatrix per-lane offsets
    const int j = lane >> 3, r = lane & 7;
    uint32_t aoff[4], boff[2];
    #pragma unroll
    for (int mi = 0; mi < 4; mi++)
        aoff[mi] = (uint32_t)(((wm * 64 + mi * 16 + (j & 1) * 8 + r) * LDT
                               + (j >> 1) * 8) * 2);
    #pragma unroll
    for (int n2 = 0; n2 < 2; n2++)
        boff[n2] = (uint32_t)((TILE_HALVES
                               + (wn * 32 + n2 * 16 + (j >> 1) * 8 + r) * LDT
                               + (j & 1) * 8) * 2);

    float acc[4][4][4];
    #pragma unroll
    for (int mi = 0; mi < 4; mi++)
        #pragma unroll
        for (int ni = 0; ni < 4; ni++)
            #pragma unroll
            for (int q = 0; q < 4; q++) acc[mi][ni][q] = 0.0f;

    auto stage_fill = [&](int kt, int st) {
        const uint32_t sb = sbase + (uint32_t)st * STAGE_BYTES;
        const size_t ko = (size_t)kt * BKH;
        cp16(sb + dA0, Ag0 + ko);
        cp16(sb + dA1, Ag1 + ko);
        cp16(sb + dB0, Bg0 + ko);
        cp16(sb + dB1, Bg1 + ko);
        CP_COMMIT();
    };

    stage_fill(0, 0);
    if (KT > 1) stage_fill(1, 1);

    for (int kt = 0; kt < KT; kt++) {
        if (kt + 1 < KT) CP_WAIT1(); else CP_WAIT0();
        __syncthreads();
        if (kt + 2 < KT) stage_fill(kt + 2, (kt + 2) % STAGES);

        const uint32_t sb = sbase + (uint32_t)(kt % STAGES) * STAGE_BYTES;
        #pragma unroll
        for (int ks = 0; ks < 2; ks++) {
            const uint32_t kk = ks * 16 * 2;   // byte offset along K
            uint32_t af[4][4];
            #pragma unroll
            for (int mi = 0; mi < 4; mi++)
                ldsm_x4(af[mi][0], af[mi][1], af[mi][2], af[mi][3],
                        sb + aoff[mi] + kk);
            uint32_t bf[4][2];
            #pragma unroll
            for (int n2 = 0; n2 < 2; n2++) {
                uint32_t b0, b1, b2, b3;
                ldsm_x4(b0, b1, b2, b3, sb + boff[n2] + kk);
                bf[n2 * 2][0] = b0; bf[n2 * 2][1] = b1;
                bf[n2 * 2 + 1][0] = b2; bf[n2 * 2 + 1][1] = b3;
            }
            #pragma unroll
            for (int mi = 0; mi < 4; mi++)
                #pragma unroll
                for (int ni = 0; ni < 4; ni++)
                    mma_f16(acc[mi][ni], af[mi], bf[ni]);
        }
        __syncthreads();
    }

    // ----------------------------- epilogue --------------------------------
    #pragma unroll
    for (int mi = 0; mi < 4; mi++) {
        #pragma unroll
        for (int ni = 0; ni < 4; ni++) {
            const int col = block_col + wn * 32 + ni * 8 + 2 * tg;
            const float b0 = bias[col], b1 = bias[col + 1];
            float sa0 = 0.f, sa1 = 0.f, sb0 = 0.f, sb1 = 0.f;
            if (MODE == 1) {
                sa0 = sigmoidf_(ga[col]);     sa1 = sigmoidf_(ga[col + 1]);
                sb0 = sigmoidf_(gb[col]);     sb1 = sigmoidf_(gb[col + 1]);
            }
            #pragma unroll
            for (int h = 0; h < 2; h++) {
                const int row = block_row + wm * 64 + mi * 16 + gr + h * 8;
                float v0 = acc[mi][ni][2 * h + 0] + b0;
                float v1 = acc[mi][ni][2 * h + 1] + b1;
                const size_t off = (size_t)row * N + col;
                if (MODE == 1) {
                    v0 = sa0 * aux[off]     + sb0 * v0;
                    v1 = sa1 * aux[off + 1] + sb1 * v1;
                } else if (MODE == 2) {
                    v0 = gelu_exact(v0);
                    v1 = gelu_exact(v1);
                } else if (MODE == 3) {
                    v0 += aux[off];
                    v1 += aux[off + 1];
                }
                if (OUT32) {
                    float2 o = make_float2(v0, v1);
                    *reinterpret_cast<float2*>(&C32[off]) = o;
                    if (MODE == 3) *reinterpret_cast<float2*>(&C32b[off]) = o;
                }
                if (OUT16)
                    *reinterpret_cast<__half2*>(&C16[off]) = __floats2half2_rn(v0, v1);
            }
        }
    }
}

// ---------------------------------------------------------------------------
// LayerNorm D=2048, fp32 in -> fp16 out
// ---------------------------------------------------------------------------
__global__ void __launch_bounds__(256) ln2048_f16(
    const float* __restrict__ x, const float* __restrict__ g,
    const float* __restrict__ b, __half* __restrict__ out)
{
    constexpr int D = 2048;
    const int row = blockIdx.x;
    const int tid = threadIdx.x;
    const float4* xr = reinterpret_cast<const float4*>(x + (size_t)row * D);

    float4 v0 = xr[tid];
    float4 v1 = xr[tid + 256];
    float s  = v0.x + v0.y + v0.z + v0.w + v1.x + v1.y + v1.z + v1.w;
    float ss = v0.x*v0.x + v0.y*v0.y + v0.z*v0.z + v0.w*v0.w
             + v1.x*v1.x + v1.y*v1.y + v1.z*v1.z + v1.w*v1.w;
    #pragma unroll
    for (int o = 16; o > 0; o >>= 1) {
        s  += __shfl_xor_sync(0xFFFFFFFFu, s,  o);
        ss += __shfl_xor_sync(0xFFFFFFFFu, ss, o);
    }
    __shared__ float sh_s[8], sh_ss[8];
    if ((tid & 31) == 0) { sh_s[tid >> 5] = s; sh_ss[tid >> 5] = ss; }
    __syncthreads();
    float ts = 0.f, tss = 0.f;
    #pragma unroll
    for (int i = 0; i < 8; i++) { ts += sh_s[i]; tss += sh_ss[i]; }
    const float mean = ts * (1.0f / D);
    const float var  = tss * (1.0f / D) - mean * mean;
    const float inv  = rsqrtf(var + 1e-5f);

    const float4* g4 = reinterpret_cast<const float4*>(g);
    const float4* b4 = reinterpret_cast<const float4*>(b);
    __half2* o2 = reinterpret_cast<__half2*>(out + (size_t)row * D);

    float4 ga0 = g4[tid],       gb0 = b4[tid];
    float4 ga1 = g4[tid + 256], gb1 = b4[tid + 256];
    o2[tid * 2]     = __floats2half2_rn((v0.x - mean) * inv * ga0.x + gb0.x,
                                        (v0.y - mean) * inv * ga0.y + gb0.y);
    o2[tid * 2 + 1] = __floats2half2_rn((v0.z - mean) * inv * ga0.z + gb0.z,
                                        (v0.w - mean) * inv * ga0.w + gb0.w);
    o2[(tid + 256) * 2]     = __floats2half2_rn((v1.x - mean) * inv * ga1.x + gb1.x,
                                                (v1.y - mean) * inv * ga1.y + gb1.y);
    o2[(tid + 256) * 2 + 1] = __floats2half2_rn((v1.z - mean) * inv * ga1.z + gb1.z,
                                                (v1.w - mean) * inv * ga1.w + gb1.w);
}

__global__ void __launch_bounds__(256) cvt_f32_f16(
    const float* __restrict__ src, __half* __restrict__ dst, int n)
{
    int i = (blockIdx.x * 256 + threadIdx.x) * 4;
    if (i < n) {
        float4 v = *reinterpret_cast<const float4*>(src + i);
        *reinterpret_cast<__half2*>(dst + i)     = __floats2half2_rn(v.x, v.y);
        *reinterpret_cast<__half2*>(dst + i + 2) = __floats2half2_rn(v.z, v.w);
    }
}

// ---------------------------------------------------------------------------
extern "C" void kernel_launch(void* const* d_in, const int* in_sizes, int n_in,
                              void* d_out, int out_size)
{
    const float* x_t    = (const float*)d_in[0];
    const float* h_prev = (const float*)d_in[1];
    const float* W_proj = (const float*)d_in[2];
    const float* b_proj = (const float*)d_in[3];
    const float* in_w   = (const float*)d_in[4];
    const float* in_b   = (const float*)d_in[5];
    const float* out_w  = (const float*)d_in[6];
    const float* out_b  = (const float*)d_in[7];
    const float* ln1_g  = (const float*)d_in[8];
    const float* ln1_b  = (const float*)d_in[9];
    const float* ln2_g  = (const float*)d_in[10];
    const float* ln2_b  = (const float*)d_in[11];
    const float* gate_a = (const float*)d_in[12];
    const float* gate_b = (const float*)d_in[13];
    const float* ffn_w1 = (const float*)d_in[14];
    const float* ffn_b1 = (const float*)d_in[15];
    const float* ffn_w2 = (const float*)d_in[16];
    const float* ffn_b2 = (const float*)d_in[17];
    float* out = (float*)d_out;

    float *px, *phh;
    __half *px16, *pqn16, *pv16, *py16, *pt16, *pwp, *pwv, *pwo, *pw1, *pw2;
    cudaGetSymbolAddress((void**)&px,    g_x);
    cudaGetSymbolAddress((void**)&phh,   g_hhat);
    cudaGetSymbolAddress((void**)&px16,  g_x16);
    cudaGetSymbolAddress((void**)&pqn16, g_qn16);
    cudaGetSymbolAddress((void**)&pv16,  g_v16);
    cudaGetSymbolAddress((void**)&py16,  g_y16);
    cudaGetSymbolAddress((void**)&pt16,  g_t16);
    cudaGetSymbolAddress((void**)&pwp,   g_wp16);
    cudaGetSymbolAddress((void**)&pwv,   g_wv16);
    cudaGetSymbolAddress((void**)&pwo,   g_wo16);
    cudaGetSymbolAddress((void**)&pw1,   g_w1_16);
    cudaGetSymbolAddress((void**)&pw2,   g_w2_16);

    cudaFuncSetAttribute(gemm16<0,1,0>, cudaFuncAttributeMaxDynamicSharedMemorySize, GSMEM);
    cudaFuncSetAttribute(gemm16<0,0,1>, cudaFuncAttributeMaxDynamicSharedMemorySize, GSMEM);
    cudaFuncSetAttribute(gemm16<1,1,0>, cudaFuncAttributeMaxDynamicSharedMemorySize, GSMEM);
    cudaFuncSetAttribute(gemm16<2,0,1>, cudaFuncAttributeMaxDynamicSharedMemorySize, GSMEM);
    cudaFuncSetAttribute(gemm16<3,1,0>, cudaFuncAttributeMaxDynamicSharedMemorySize, GSMEM);

    // fp32 -> fp16 conversions
    cvt_f32_f16<<<(B_DIM*1024)/1024, 256>>>(x_t, px16, B_DIM*1024);
    cvt_f32_f16<<<(D_MODEL*1024)/1024, 256>>>(W_proj, pwp, D_MODEL*1024);
    cvt_f32_f16<<<(D_MODEL*D_MODEL)/1024, 256>>>(in_w + (size_t)2*D_MODEL*D_MODEL, pwv,
                                                 D_MODEL*D_MODEL);
    cvt_f32_f16<<<(D_MODEL*D_MODEL)/1024, 256>>>(out_w, pwo, D_MODEL*D_MODEL);
    cvt_f32_f16<<<(D_FF*D_MODEL)/1024, 256>>>(ffn_w1, pw1, D_FF*D_MODEL);
    cvt_f32_f16<<<(D_MODEL*D_FF)/1024, 256>>>(ffn_w2, pw2, D_MODEL*D_FF);

    const dim3 blk(256);
    const dim3 gD(D_MODEL/BN, B_DIM/BM);   // 16 x 32
    const dim3 gF(D_FF/BN,    B_DIM/BM);   // 64 x 32

    gemm16<0,1,0><<<gD, blk, GSMEM>>>(px16, pwp, b_proj, px, nullptr, nullptr,
                                      nullptr, nullptr, nullptr, D_MODEL, 1024);
    ln2048_f16<<<B_DIM, 256>>>(px, ln1_g, ln1_b, pqn16);
    gemm16<0,0,1><<<gD, blk, GSMEM>>>(pqn16, pwv, in_b + 2*D_MODEL, nullptr, pv16,
                                      nullptr, nullptr, nullptr, nullptr,
                                      D_MODEL, D_MODEL);
    gemm16<1,1,0><<<gD, blk, GSMEM>>>(pv16, pwo, out_b, phh, nullptr, nullptr,
                                      h_prev, gate_a, gate_b, D_MODEL, D_MODEL);
    ln2048_f16<<<B_DIM, 256>>>(phh, ln2_g, ln2_b, py16);
    gemm16<2,0,1><<<gF, blk, GSMEM>>>(py16, pw1, ffn_b1, nullptr, pt16, nullptr,
                                      nullptr, nullptr, nullptr, D_FF, D_MODEL);
    float* out2 = (out_size >= 2 * B_DIM * D_MODEL) ? (out + (size_t)B_DIM * D_MODEL) : out;
    gemm16<3,1,0><<<gD, blk, GSMEM>>>(pt16, pw2, ffn_b2, out, nullptr, out2,
                                      phh, nullptr, nullptr, D_MODEL, D_FF);
}